// round 13
// baseline (speedup 1.0000x reference)
#include <cuda_runtime.h>

// ChamferLoss: pred[2048,8,3], gt[2048,8,3] -> scalar
// d2 = |x|^2 + min_y(|y|^2 - 2 x.y); sqrt is monotone -> one sqrt per query.
// Packed f32x2 FMA: 2 targets per chain. 4 queries per thread share each
// smem target load. 256 thr/block (2 warps/SMSP), unroll-8 for deep ILP.

typedef unsigned long long ull;

__device__ __forceinline__ ull pack2(float lo, float hi) {
    ull r; asm("mov.b64 %0,{%1,%2};" : "=l"(r) : "f"(lo), "f"(hi)); return r;
}
__device__ __forceinline__ ull fma2(ull a, ull b, ull c) {
    ull d; asm("fma.rn.f32x2 %0,%1,%2,%3;" : "=l"(d) : "l"(a), "l"(b), "l"(c)); return d;
}
__device__ __forceinline__ void unpack2(ull v, float& lo, float& hi) {
    asm("mov.b64 {%0,%1},%2;" : "=f"(lo), "=f"(hi) : "l"(v));
}
__device__ __forceinline__ void cpa16(unsigned dst, const void* src) {
    asm volatile("cp.async.cg.shared.global [%0], [%1], 16;" :: "r"(dst), "l"(src));
}
__device__ __forceinline__ void cpa_commit() { asm volatile("cp.async.commit_group;"); }
__device__ __forceinline__ void cpa_wait1() { asm volatile("cp.async.wait_group 1;"); }
__device__ __forceinline__ void cpa_wait0() { asm volatile("cp.async.wait_group 0;"); }

#define NPAIR        8192               // packed target pairs per direction
#define TILE_PAIRS   2048
#define TILE_ENTRIES (2 * TILE_PAIRS)   // ulonglong2 entries per tile (64 KB)
#define NTILES       (NPAIR / TILE_PAIRS)
#define MAIN_BLOCKS  128
#define MAIN_THREADS 256
#define SLICES       4
#define SLICE_PAIRS  (TILE_PAIRS / SLICES)   // 512 pairs per slice per tile
#define SMEM_BYTES   (2 * TILE_ENTRIES * 16) // 128 KB double buffer

// Packed targets: pair p -> entry 2p = {pack(y0a,y0b), pack(y1a,y1b)},
// entry 2p+1 = {pack(y2a,y2b), pack(|ya|^2,|yb|^2)}. dir0 targets=gt, dir1=pred.
__device__ ulonglong2 g_tgt[2][2 * NPAIR];
__device__ float g_partial[MAIN_BLOCKS];
__device__ unsigned g_count;

__global__ void prep_kernel(const float* __restrict__ pred,
                            const float* __restrict__ gt) {
    int pid = blockIdx.x * blockDim.x + threadIdx.x;   // 0..16383
    int d   = pid >> 13;
    int p   = pid & (NPAIR - 1);
    const float* src = (d == 0) ? gt : pred;
    const float* t0 = src + (2 * p) * 3;
    const float* t1 = src + (2 * p + 1) * 3;
    float a0 = t0[0], a1 = t0[1], a2 = t0[2];
    float b0 = t1[0], b1 = t1[1], b2 = t1[2];
    float na = a0 * a0 + a1 * a1 + a2 * a2;
    float nb = b0 * b0 + b1 * b1 + b2 * b2;
    ulonglong2 e0, e1;
    e0.x = pack2(a0, b0); e0.y = pack2(a1, b1);
    e1.x = pack2(a2, b2); e1.y = pack2(na, nb);
    g_tgt[d][2 * p]     = e0;
    g_tgt[d][2 * p + 1] = e1;
}

__global__ void __launch_bounds__(MAIN_THREADS, 1)
chamfer_main(const float* __restrict__ pred, const float* __restrict__ gt,
             float* __restrict__ out) {
    extern __shared__ ulonglong2 sm[];      // [2][TILE_ENTRIES]
    __shared__ float red[64];
    __shared__ unsigned isLast;

    int t   = threadIdx.x;
    int dir = blockIdx.x >> 6;              // 0: queries=pred, 1: queries=gt
    int sub = blockIdx.x & 63;
    int s   = t >> 6;                       // target slice 0..3 (warp-uniform)
    int qi  = t & 63;

    const float* qsrc = (dir == 0) ? pred : gt;
    int qbase = sub * 256 + qi * 4;

    ull  A[4][3];
    float n[4];
#pragma unroll
    for (int j = 0; j < 4; j++) {
        int q = qbase + j;
        float x0 = qsrc[3 * q], x1 = qsrc[3 * q + 1], x2 = qsrc[3 * q + 2];
        n[j] = x0 * x0 + x1 * x1 + x2 * x2;
        A[j][0] = pack2(-2.0f * x0, -2.0f * x0);
        A[j][1] = pack2(-2.0f * x1, -2.0f * x1);
        A[j][2] = pack2(-2.0f * x2, -2.0f * x2);
    }

    float mlo[4], mhi[4];
#pragma unroll
    for (int j = 0; j < 4; j++) { mlo[j] = 3.0e38f; mhi[j] = 3.0e38f; }

    const ulonglong2* g = g_tgt[dir];
    unsigned sbase = (unsigned)__cvta_generic_to_shared(sm);

    // prefetch tiles 0 and 1
#pragma unroll
    for (int i = 0; i < TILE_ENTRIES / MAIN_THREADS; i++) {
        int e = t + i * MAIN_THREADS;
        cpa16(sbase + (unsigned)(0 * TILE_ENTRIES + e) * 16, g + 0 * TILE_ENTRIES + e);
    }
    cpa_commit();
#pragma unroll
    for (int i = 0; i < TILE_ENTRIES / MAIN_THREADS; i++) {
        int e = t + i * MAIN_THREADS;
        cpa16(sbase + (unsigned)(1 * TILE_ENTRIES + e) * 16, g + 1 * TILE_ENTRIES + e);
    }
    cpa_commit();

    for (int T = 0; T < NTILES; T++) {
        if (T < NTILES - 1) cpa_wait1(); else cpa_wait0();
        __syncthreads();

        const ulonglong2* B = sm + (T & 1) * TILE_ENTRIES + s * (2 * SLICE_PAIRS);
        // Deep unroll: 16 broadcast LDS.128 front-batched per body, 32
        // independent FFMA2 chains -> covers LDS 29cyc + 12cyc chain latency.
#pragma unroll 8
        for (int p = 0; p < SLICE_PAIRS; p++) {
            ulonglong2 E0 = B[2 * p];       // broadcast across warp (same addr)
            ulonglong2 E1 = B[2 * p + 1];
#pragma unroll
            for (int j = 0; j < 4; j++) {
                ull tt = fma2(A[j][2], E1.x, E1.y);
                tt     = fma2(A[j][1], E0.y, tt);
                tt     = fma2(A[j][0], E0.x, tt);
                float lo, hi;
                unpack2(tt, lo, hi);
                mlo[j] = fminf(mlo[j], lo);
                mhi[j] = fminf(mhi[j], hi);
            }
        }

        if (T < NTILES - 2) {
            __syncthreads();   // everyone done reading buffer (T&1) before overwrite
#pragma unroll
            for (int i = 0; i < TILE_ENTRIES / MAIN_THREADS; i++) {
                int e = t + i * MAIN_THREADS;
                cpa16(sbase + (unsigned)((T & 1) * TILE_ENTRIES + e) * 16,
                      g + (T + 2) * TILE_ENTRIES + e);
            }
            cpa_commit();
        }
    }

    __syncthreads();
    float* pm = (float*)sm;                 // reuse tile smem: [4][64][4]
#pragma unroll
    for (int j = 0; j < 4; j++)
        pm[(s * 64 + qi) * 4 + j] = fminf(mlo[j], mhi[j]);
    __syncthreads();

    if (t < 64) {
        float sum = 0.0f;
#pragma unroll
        for (int j = 0; j < 4; j++) {
            float mm = pm[(0 * 64 + t) * 4 + j];
#pragma unroll
            for (int ss = 1; ss < SLICES; ss++)
                mm = fminf(mm, pm[(ss * 64 + t) * 4 + j]);
            sum += sqrtf(fmaxf(n[j] + mm, 0.0f));   // s==0 threads own these queries
        }
        red[t] = sum * (1.0f / 16384.0f);
    }
    __syncthreads();
#pragma unroll
    for (int st = 32; st > 0; st >>= 1) {
        if (t < st) red[t] += red[t + st];
        __syncthreads();
    }
    if (t == 0) g_partial[blockIdx.x] = red[0];

    // fused final reduction: last block to finish sums all partials (fixed
    // order -> deterministic). g_count returns to 0 for the next replay.
    if (t == 0) {
        __threadfence();
        unsigned c = atomicAdd(&g_count, 1u);
        isLast = (c == MAIN_BLOCKS - 1) ? 1u : 0u;
    }
    __syncthreads();
    if (isLast) {
        if (t < 64) red[t] = g_partial[t] + g_partial[t + 64];
        __syncthreads();
#pragma unroll
        for (int st = 32; st > 0; st >>= 1) {
            if (t < st) red[t] += red[t + st];
            __syncthreads();
        }
        if (t == 0) { out[0] = red[0]; g_count = 0; }
    }
}

extern "C" void kernel_launch(void* const* d_in, const int* in_sizes, int n_in,
                              void* d_out, int out_size) {
    const float* pred = (const float*)d_in[0];
    const float* gt   = (const float*)d_in[1];
    cudaFuncSetAttribute(chamfer_main, cudaFuncAttributeMaxDynamicSharedMemorySize,
                         SMEM_BYTES);
    prep_kernel<<<64, 256>>>(pred, gt);
    chamfer_main<<<MAIN_BLOCKS, MAIN_THREADS, SMEM_BYTES>>>(pred, gt, (float*)d_out);
}

// round 17
// speedup vs baseline: 1.2062x; 1.2062x over previous
#include <cuda_runtime.h>

// ChamferLoss: pred[2048,8,3], gt[2048,8,3] -> scalar
// Single-pass bidirectional: each (pred,gt) pair evaluated ONCE.
//   w = |x|^2 + |y|^2 - 2 x.y   (packed f32x2: 2 gt targets per chain)
//   row-min (per pred point): register accumulators per thread (4 queries).
//   col-min (per gt point): fold 4 queries (FMNMX) then 32 lanes via
//   redux.sync.min.s32 on raw float bits (valid: w >= -eps; negatives clamp
//   to 0 in sqrt(max(w,0)) so ordering among them is irrelevant).
// Block-partial col-mins -> g_colpart[128][16384], reduced in pass2.

typedef unsigned long long ull;

__device__ __forceinline__ ull pack2(float lo, float hi) {
    ull r; asm("mov.b64 %0,{%1,%2};" : "=l"(r) : "f"(lo), "f"(hi)); return r;
}
__device__ __forceinline__ ull fma2(ull a, ull b, ull c) {
    ull d; asm("fma.rn.f32x2 %0,%1,%2,%3;" : "=l"(d) : "l"(a), "l"(b), "l"(c)); return d;
}
__device__ __forceinline__ ull add2(ull a, ull b) {
    ull d; asm("add.rn.f32x2 %0,%1,%2;" : "=l"(d) : "l"(a), "l"(b)); return d;
}
__device__ __forceinline__ void unpack2(ull v, float& lo, float& hi) {
    asm("mov.b64 {%0,%1},%2;" : "=f"(lo), "=f"(hi) : "l"(v));
}
__device__ __forceinline__ int redux_min(int v) {
    int r; asm("redux.sync.min.s32 %0, %1, 0xffffffff;" : "=r"(r) : "r"(v)); return r;
}
__device__ __forceinline__ void cpa16(unsigned dst, const void* src) {
    asm volatile("cp.async.cg.shared.global [%0], [%1], 16;" :: "r"(dst), "l"(src));
}
__device__ __forceinline__ void cpa_commit() { asm volatile("cp.async.commit_group;"); }
__device__ __forceinline__ void cpa_wait1() { asm volatile("cp.async.wait_group 1;"); }
__device__ __forceinline__ void cpa_wait0() { asm volatile("cp.async.wait_group 0;"); }

#define NPTS         16384
#define NPAIR        8192               // gt target pairs
#define TILE_PAIRS   2048
#define TILE_ENTRIES (2 * TILE_PAIRS)   // ulonglong2 entries per tile (64 KB)
#define NTILES       (NPAIR / TILE_PAIRS)
#define MAIN_BLOCKS  128
#define MAIN_THREADS 256
#define SLICES       8
#define SLICE_PAIRS  (TILE_PAIRS / SLICES)    // 256 pairs per warp per tile
#define SMEM_TILE_BYTES (2 * TILE_ENTRIES * 16)   // 128 KB double buffer
#define COLBUF_BYTES    (TILE_PAIRS * 8)          // int2 per pair, 16 KB
#define SMEM_BYTES      (SMEM_TILE_BYTES + COLBUF_BYTES)

// Packed gt targets: pair p -> entry 2p = {pack(y0a,y0b), pack(y1a,y1b)},
// entry 2p+1 = {pack(y2a,y2b), pack(|ya|^2,|yb|^2)}.
__device__ ulonglong2 g_tgt[2 * NPAIR];
__device__ int   g_colpart[MAIN_BLOCKS][NPTS];   // per-block col-min (float bits)
__device__ float g_rowsum[MAIN_BLOCKS];
__device__ float g_colsum[MAIN_BLOCKS];
__device__ unsigned g_count2;

__global__ void prep_kernel(const float* __restrict__ gt) {
    int p = blockIdx.x * blockDim.x + threadIdx.x;   // 0..8191
    const float* t0 = gt + (2 * p) * 3;
    const float* t1 = gt + (2 * p + 1) * 3;
    float a0 = t0[0], a1 = t0[1], a2 = t0[2];
    float b0 = t1[0], b1 = t1[1], b2 = t1[2];
    float na = a0 * a0 + a1 * a1 + a2 * a2;
    float nb = b0 * b0 + b1 * b1 + b2 * b2;
    ulonglong2 e0, e1;
    e0.x = pack2(a0, b0); e0.y = pack2(a1, b1);
    e1.x = pack2(a2, b2); e1.y = pack2(na, nb);
    g_tgt[2 * p]     = e0;
    g_tgt[2 * p + 1] = e1;
}

__global__ void __launch_bounds__(MAIN_THREADS, 1)
chamfer_main(const float* __restrict__ pred) {
    extern __shared__ ulonglong2 sm[];          // [2][TILE_ENTRIES] then colbuf
    int2* colbuf = (int2*)(sm + 2 * TILE_ENTRIES);   // [TILE_PAIRS]
    __shared__ float red[32];

    int t    = threadIdx.x;
    int s    = t >> 5;            // warp = target slice 0..7
    int lane = t & 31;

    int qbase = blockIdx.x * 128 + lane * 4;    // 4 pred queries per thread
    ull A[4][3], n2[4];
#pragma unroll
    for (int j = 0; j < 4; j++) {
        int q = qbase + j;
        float x0 = pred[3 * q], x1 = pred[3 * q + 1], x2 = pred[3 * q + 2];
        float nn = x0 * x0 + x1 * x1 + x2 * x2;
        n2[j]   = pack2(nn, nn);
        A[j][0] = pack2(-2.0f * x0, -2.0f * x0);
        A[j][1] = pack2(-2.0f * x1, -2.0f * x1);
        A[j][2] = pack2(-2.0f * x2, -2.0f * x2);
    }

    float mlo[4], mhi[4];
#pragma unroll
    for (int j = 0; j < 4; j++) { mlo[j] = 3.0e38f; mhi[j] = 3.0e38f; }

    unsigned sbase = (unsigned)__cvta_generic_to_shared(sm);

    // prefetch tiles 0 and 1
#pragma unroll
    for (int i = 0; i < TILE_ENTRIES / MAIN_THREADS; i++) {
        int e = t + i * MAIN_THREADS;
        cpa16(sbase + (unsigned)(0 * TILE_ENTRIES + e) * 16, g_tgt + 0 * TILE_ENTRIES + e);
    }
    cpa_commit();
#pragma unroll
    for (int i = 0; i < TILE_ENTRIES / MAIN_THREADS; i++) {
        int e = t + i * MAIN_THREADS;
        cpa16(sbase + (unsigned)(1 * TILE_ENTRIES + e) * 16, g_tgt + 1 * TILE_ENTRIES + e);
    }
    cpa_commit();

    for (int T = 0; T < NTILES; T++) {
        if (T < NTILES - 1) cpa_wait1(); else cpa_wait0();
        __syncthreads();

        const ulonglong2* B = sm + (T & 1) * TILE_ENTRIES + s * (2 * SLICE_PAIRS);
#pragma unroll 4
        for (int p = 0; p < SLICE_PAIRS; p++) {
            ulonglong2 E0 = B[2 * p];       // warp-broadcast
            ulonglong2 E1 = B[2 * p + 1];
            float colLo, colHi;
#pragma unroll
            for (int j = 0; j < 4; j++) {
                ull tt = fma2(A[j][2], E1.x, E1.y);
                tt     = fma2(A[j][1], E0.y, tt);
                tt     = fma2(A[j][0], E0.x, tt);
                ull w  = add2(tt, n2[j]);           // full d^2 (2 targets)
                float lo, hi;
                unpack2(w, lo, hi);
                mlo[j] = fminf(mlo[j], lo);         // row-min accumulators
                mhi[j] = fminf(mhi[j], hi);
                if (j == 0) { colLo = lo; colHi = hi; }
                else        { colLo = fminf(colLo, lo); colHi = fminf(colHi, hi); }
            }
            // col-min across this block's 128 queries (4 per lane * 32 lanes)
            int klo = redux_min(__float_as_int(colLo));
            int khi = redux_min(__float_as_int(colHi));
            if (lane == 0) colbuf[s * SLICE_PAIRS + p] = make_int2(klo, khi);
        }
        __syncthreads();   // compute + colbuf writes done; tile buffer reusable

        // flush this tile's block-partial col-mins (coalesced)
        {
            int2* dst = (int2*)&g_colpart[blockIdx.x][T * (2 * TILE_PAIRS)];
#pragma unroll
            for (int i = 0; i < TILE_PAIRS / MAIN_THREADS; i++)
                dst[t + i * MAIN_THREADS] = colbuf[t + i * MAIN_THREADS];
        }

        if (T < NTILES - 2) {
#pragma unroll
            for (int i = 0; i < TILE_ENTRIES / MAIN_THREADS; i++) {
                int e = t + i * MAIN_THREADS;
                cpa16(sbase + (unsigned)((T & 1) * TILE_ENTRIES + e) * 16,
                      g_tgt + (T + 2) * TILE_ENTRIES + e);
            }
            cpa_commit();
        }
    }

    __syncthreads();
    float* pm = (float*)sm;                 // reuse tile smem: [8][32][4]
#pragma unroll
    for (int j = 0; j < 4; j++)
        pm[(s * 32 + lane) * 4 + j] = fminf(mlo[j], mhi[j]);
    __syncthreads();

    if (t < 32) {
        float sum = 0.0f;
#pragma unroll
        for (int j = 0; j < 4; j++) {
            float mm = pm[(0 * 32 + t) * 4 + j];
#pragma unroll
            for (int ss = 1; ss < SLICES; ss++)
                mm = fminf(mm, pm[(ss * 32 + t) * 4 + j]);
            sum += sqrtf(fmaxf(mm, 0.0f));
        }
        red[t] = sum;
    }
    __syncthreads();
    if (t < 16) red[t] += red[t + 16];
    __syncthreads();
    if (t < 8)  red[t] += red[t + 8];
    __syncthreads();
    if (t < 4)  red[t] += red[t + 4];
    __syncthreads();
    if (t == 0) g_rowsum[blockIdx.x] = red[0] + red[1] + red[2] + red[3];
}

__global__ void __launch_bounds__(128)
pass2_kernel(float* __restrict__ out) {
    __shared__ float red[128];
    __shared__ unsigned isLast;
    int t   = threadIdx.x;
    int tgt = blockIdx.x * 128 + t;

    // min over 128 block-partials; 4 interleaved chains for MLP/latency
    int m0 = g_colpart[0][tgt], m1 = g_colpart[1][tgt];
    int m2 = g_colpart[2][tgt], m3 = g_colpart[3][tgt];
#pragma unroll 8
    for (int k = 4; k < MAIN_BLOCKS; k += 4) {
        m0 = min(m0, g_colpart[k][tgt]);
        m1 = min(m1, g_colpart[k + 1][tgt]);
        m2 = min(m2, g_colpart[k + 2][tgt]);
        m3 = min(m3, g_colpart[k + 3][tgt]);
    }
    int mk = min(min(m0, m1), min(m2, m3));
    float w = __int_as_float(mk);
    red[t] = sqrtf(fmaxf(w, 0.0f));
    __syncthreads();
#pragma unroll
    for (int st = 64; st > 0; st >>= 1) {
        if (t < st) red[t] += red[t + st];
        __syncthreads();
    }
    if (t == 0) g_colsum[blockIdx.x] = red[0];

    if (t == 0) {
        __threadfence();
        unsigned c = atomicAdd(&g_count2, 1u);
        isLast = (c == MAIN_BLOCKS - 1) ? 1u : 0u;
    }
    __syncthreads();
    if (isLast) {
        __threadfence();
        red[t] = g_colsum[t] + g_rowsum[t];
        __syncthreads();
#pragma unroll
        for (int st = 64; st > 0; st >>= 1) {
            if (t < st) red[t] += red[t + st];
            __syncthreads();
        }
        if (t == 0) { out[0] = red[0] * (1.0f / 16384.0f); g_count2 = 0; }
    }
}

extern "C" void kernel_launch(void* const* d_in, const int* in_sizes, int n_in,
                              void* d_out, int out_size) {
    const float* pred = (const float*)d_in[0];
    const float* gt   = (const float*)d_in[1];
    cudaFuncSetAttribute(chamfer_main, cudaFuncAttributeMaxDynamicSharedMemorySize,
                         SMEM_BYTES);
    prep_kernel<<<32, 256>>>(gt);
    chamfer_main<<<MAIN_BLOCKS, MAIN_THREADS, SMEM_BYTES>>>(pred);
    pass2_kernel<<<MAIN_BLOCKS, 128>>>((float*)d_out);
}